// round 6
// baseline (speedup 1.0000x reference)
#include <cuda_runtime.h>

// out = foldl over T slices: s = (1-lam)*s + lam*adj[t], s0 = adj[0]
// Pure HBM streaming (272 MB @ T=16, N=2048).
// Persistent grid-stride: exactly one wave (152 SMs x 8 CTAs = 1216 blocks),
// zero wave transitions, per-block prologue paid once. Coalescing identical
// to the wave-launched version. Recurrence form (bit-exact vs reference).

#define NUM_SMS 152
#define CTAS_PER_SM 8
#define PERSISTENT_BLOCKS (NUM_SMS * CTAS_PER_SM)

template <int T>
__global__ void __launch_bounds__(256, 8)
ema_fold_kernel(const float4* __restrict__ adj,
                const float* __restrict__ lam_p,
                float4* __restrict__ out,
                int n4) {
    const float lam = __ldg(lam_p);
    const float om  = 1.0f - lam;

    const int stride = gridDim.x * blockDim.x;
    for (int i = blockIdx.x * blockDim.x + threadIdx.x; i < n4; i += stride) {
        const float4* p = adj + i;
        float4 s = __ldcs(p);
#pragma unroll
        for (int t = 1; t < T; ++t) {
            float4 v = __ldcs(p + (size_t)t * (size_t)n4);
            s.x = fmaf(om, s.x, lam * v.x);
            s.y = fmaf(om, s.y, lam * v.y);
            s.z = fmaf(om, s.z, lam * v.z);
            s.w = fmaf(om, s.w, lam * v.w);
        }
        __stcs(out + i, s);
    }
}

// Generic-T fallback (runtime T), grid-stride.
__global__ void __launch_bounds__(256, 8)
ema_fold_generic(const float4* __restrict__ adj,
                 const float* __restrict__ lam_p,
                 float4* __restrict__ out,
                 int n4, int T) {
    const float lam = __ldg(lam_p);
    const float om  = 1.0f - lam;

    const int stride = gridDim.x * blockDim.x;
    for (int i = blockIdx.x * blockDim.x + threadIdx.x; i < n4; i += stride) {
        const float4* p = adj + i;
        float4 s = __ldcs(p);
        for (int t = 1; t < T; ++t) {
            float4 v = __ldcs(p + (size_t)t * (size_t)n4);
            s.x = fmaf(om, s.x, lam * v.x);
            s.y = fmaf(om, s.y, lam * v.y);
            s.z = fmaf(om, s.z, lam * v.z);
            s.w = fmaf(om, s.w, lam * v.w);
        }
        __stcs(out + i, s);
    }
}

extern "C" void kernel_launch(void* const* d_in, const int* in_sizes, int n_in,
                              void* d_out, int out_size) {
    const float4* adj  = (const float4*)d_in[0];
    const float*  lamp = (const float*)d_in[1];
    float4*       out  = (float4*)d_out;

    const int total = in_sizes[0];        // T * N * N
    const int T     = total / out_size;   // leading axis length
    const int n4    = out_size / 4;       // float4 elements per slice

    const int threads = 256;
    // One full wave; never launch more blocks than chunks.
    int blocks = PERSISTENT_BLOCKS;
    const int chunks = (n4 + threads - 1) / threads;
    if (blocks > chunks) blocks = chunks;

    if (T == 16) {
        ema_fold_kernel<16><<<blocks, threads>>>(adj, lamp, out, n4);
    } else {
        ema_fold_generic<<<blocks, threads>>>(adj, lamp, out, n4, T);
    }
}